// round 1
// baseline (speedup 1.0000x reference)
#include <cuda_runtime.h>
#include <cuda_bf16.h>

// diag-embed: out[i, j, k] = (j == k) ? x[i, j] : 0
// x: [8192, 176] fp32, out: [8192, 176, 176] fp32 (~1.015 GB of stores).
// Pure HBM-store-bound. One float4 (STG.128) per thread; the single nonzero
// per 176-float output row is spliced into the right lane.

#define D_MODEL 176
#define CHUNKS_PER_ROW (D_MODEL / 4)   // 44 float4 per output row

__global__ void diag_embed_kernel(const float* __restrict__ x,
                                  float4* __restrict__ out,
                                  long long n4) {
    long long g = (long long)blockIdx.x * blockDim.x + threadIdx.x;
    if (g >= n4) return;

    // g indexes 16-byte chunks. Each output row (i, j) has 44 chunks.
    int q = (int)(g % CHUNKS_PER_ROW);            // chunk within row
    long long rowg = g / CHUNKS_PER_ROW;          // global row = i*176 + j
    int row = (int)(rowg % D_MODEL);              // j (diag position)

    float4 v = make_float4(0.f, 0.f, 0.f, 0.f);
    if (q == (row >> 2)) {
        // diagonal element lives in this chunk; x[i*176 + j] == x[rowg]
        float xv = __ldg(&x[rowg]);
        ((float*)&v)[row & 3] = xv;
    }
    out[g] = v;
}

extern "C" void kernel_launch(void* const* d_in, const int* in_sizes, int n_in,
                              void* d_out, int out_size) {
    const float* x = (const float*)d_in[0];
    float4* out = (float4*)d_out;

    long long n4 = (long long)out_size / 4;  // total float4 chunks
    int threads = 256;
    long long blocks = (n4 + threads - 1) / threads;

    diag_embed_kernel<<<(unsigned int)blocks, threads>>>(x, out, n4);
}

// round 2
// speedup vs baseline: 1.2212x; 1.2212x over previous
#include <cuda_runtime.h>
#include <cuda_bf16.h>

// diag-embed: out[i, j, k] = (j == k) ? x[i, j] : 0
// x: [8192, 176] fp32, out: [8192, 176, 176] fp32 (~1.015 GB of stores).
//
// R2: pure HBM-store-bound. Persistent grid-stride kernel, one STG.128 per
// chunk, ALL index math in 32-bit (magic-div), unroll 4. Fixed grid keeps
// warps resident and stores streaming; index cost per 16B store drops from
// ~25 instrs (64-bit div/mod) to ~8.

#define D_MODEL 176u
#define CHUNKS_PER_ROW 44u   // 176/4 float4 chunks per output row

__global__ __launch_bounds__(256) void diag_embed_kernel(
        const float* __restrict__ x,
        float4* __restrict__ out,
        unsigned n4) {
    const unsigned stride = gridDim.x * blockDim.x;
    unsigned g = blockIdx.x * blockDim.x + threadIdx.x;

    #pragma unroll 4
    for (; g < n4; g += stride) {
        unsigned rowg = g / CHUNKS_PER_ROW;        // 32-bit magic div
        unsigned q    = g - rowg * CHUNKS_PER_ROW; // chunk within row
        unsigned row  = rowg % D_MODEL;            // 32-bit magic mod

        float4 v = make_float4(0.f, 0.f, 0.f, 0.f);
        if (q == (row >> 2)) {
            float xv = __ldg(&x[rowg]);            // L2-hot (x is 5.8 MB)
            ((float*)&v)[row & 3u] = xv;
        }
        out[g] = v;
    }
}

extern "C" void kernel_launch(void* const* d_in, const int* in_sizes, int n_in,
                              void* d_out, int out_size) {
    const float* x = (const float*)d_in[0];
    float4* out = (float4*)d_out;

    unsigned n4 = (unsigned)(out_size / 4);  // total float4 chunks (63,438,848)

    // Persistent grid: 148 SMs x 8 blocks x 256 threads (16 regs -> fits easily)
    int blocks = 148 * 8;
    diag_embed_kernel<<<blocks, 256>>>(x, out, n4);
}